// round 10
// baseline (speedup 1.0000x reference)
#include <cuda_runtime.h>
#include <cuda_bf16.h>
#include <math.h>
#include <stdint.h>

// Problem constants
#define PB   4
#define PS   2048
#define PH   1024      // hidden = NH*HD
#define PNH  16
#define PHD  64
#define PWH  32        // window half = WIN//2
#define PM   (PB*PS)   // 8192 GEMM rows

// Scratch (allocation-free): q, k, v, attn-out, each [B,S,NH*HD] fp32
#define SCR_ELEMS (PB*PS*PH)
__device__ float g_q[SCR_ELEMS];
__device__ float g_k[SCR_ELEMS];
__device__ float g_v[SCR_ELEMS];
__device__ float g_a[SCR_ELEMS];

// ---------------------------------------------------------------------------
// TF32 helpers
// ---------------------------------------------------------------------------
__device__ __forceinline__ float to_tf32(float x) {
    uint32_t u;
    asm("cvt.rna.tf32.f32 %0, %1;" : "=r"(u) : "f"(x));
    return __uint_as_float(u);
}

__device__ __forceinline__ void mma_tf32(float* c, const float* a, const float* b) {
    asm volatile(
        "mma.sync.aligned.m16n8k8.row.col.f32.tf32.tf32.f32 "
        "{%0,%1,%2,%3}, {%4,%5,%6,%7}, {%8,%9}, {%0,%1,%2,%3};"
        : "+f"(c[0]), "+f"(c[1]), "+f"(c[2]), "+f"(c[3])
        : "r"(__float_as_uint(a[0])), "r"(__float_as_uint(a[1])),
          "r"(__float_as_uint(a[2])), "r"(__float_as_uint(a[3])),
          "r"(__float_as_uint(b[0])), "r"(__float_as_uint(b[1])));
}

// ---------------------------------------------------------------------------
// GEMM (TF32 mma.sync, R6-identical math): C = A @ W + bias.
// 128x128 block, BK=16, 8 warps (2m x 4n), warp tile 64x32, m16n8k8.
// blockIdx.z selects among up to 3 operand sets (fused QKV launch).
// ---------------------------------------------------------------------------
#define GK 1024
#define GN 1024

__global__ __launch_bounds__(256) void gemm_tf32_multi(
    const float* __restrict__ A,
    const float* __restrict__ W0, const float* __restrict__ b0, float* __restrict__ C0,
    const float* __restrict__ W1, const float* __restrict__ b1, float* __restrict__ C1,
    const float* __restrict__ W2, const float* __restrict__ b2, float* __restrict__ C2)
{
    const float* W    = (blockIdx.z == 0) ? W0 : (blockIdx.z == 1) ? W1 : W2;
    const float* bias = (blockIdx.z == 0) ? b0 : (blockIdx.z == 1) ? b1 : b2;
    float*       C    = (blockIdx.z == 0) ? C0 : (blockIdx.z == 1) ? C1 : C2;

    __shared__ float As[16][128];   // [k][m] transposed on store
    __shared__ float Bs[16][128];   // [k][n]

    const int tid = threadIdx.x;
    const int m0 = blockIdx.y * 128;
    const int n0 = blockIdx.x * 128;
    const int warp = tid >> 5;
    const int lane = tid & 31;
    const int g  = lane >> 2;
    const int tg = lane & 3;
    const int wm = (warp & 1) * 64;
    const int wn = (warp >> 1) * 32;

    float acc[4][4][4];
    #pragma unroll
    for (int mi = 0; mi < 4; mi++)
        #pragma unroll
        for (int ni = 0; ni < 4; ni++)
            #pragma unroll
            for (int r = 0; r < 4; r++) acc[mi][ni][r] = 0.f;

    const float* Ab = A + (size_t)m0 * GK;
    const float* Wb = W + n0;

    for (int k0 = 0; k0 < GK; k0 += 16) {
        #pragma unroll
        for (int i = 0; i < 2; i++) {
            int idx = tid + i * 256;
            int r  = idx >> 2;
            int c4 = (idx & 3) << 2;
            float4 av = *(const float4*)(Ab + (size_t)r * GK + k0 + c4);
            As[c4 + 0][r] = to_tf32(av.x);
            As[c4 + 1][r] = to_tf32(av.y);
            As[c4 + 2][r] = to_tf32(av.z);
            As[c4 + 3][r] = to_tf32(av.w);
        }
        #pragma unroll
        for (int i = 0; i < 2; i++) {
            int idx = tid + i * 256;
            int r  = idx >> 5;
            int c4 = (idx & 31) << 2;
            float4 v = *(const float4*)(Wb + (size_t)(k0 + r) * GN + c4);
            v.x = to_tf32(v.x); v.y = to_tf32(v.y);
            v.z = to_tf32(v.z); v.w = to_tf32(v.w);
            *(float4*)(&Bs[r][c4]) = v;
        }
        __syncthreads();

        #pragma unroll
        for (int ks = 0; ks < 2; ks++) {
            const int kb = ks * 8;
            float af[4][4], bf[4][2];
            #pragma unroll
            for (int mi = 0; mi < 4; mi++) {
                const int mr = wm + mi * 16 + g;
                af[mi][0] = As[kb + tg    ][mr];
                af[mi][1] = As[kb + tg    ][mr + 8];
                af[mi][2] = As[kb + tg + 4][mr];
                af[mi][3] = As[kb + tg + 4][mr + 8];
            }
            #pragma unroll
            for (int ni = 0; ni < 4; ni++) {
                const int nc = wn + ni * 8 + g;
                bf[ni][0] = Bs[kb + tg    ][nc];
                bf[ni][1] = Bs[kb + tg + 4][nc];
            }
            #pragma unroll
            for (int mi = 0; mi < 4; mi++)
                #pragma unroll
                for (int ni = 0; ni < 4; ni++)
                    mma_tf32(acc[mi][ni], af[mi], bf[ni]);
        }
        __syncthreads();
    }

    #pragma unroll
    for (int mi = 0; mi < 4; mi++) {
        const int row0 = m0 + wm + mi * 16 + g;
        #pragma unroll
        for (int ni = 0; ni < 4; ni++) {
            const int col = n0 + wn + ni * 8 + tg * 2;
            const float2 bv = *(const float2*)(bias + col);
            float2 o0, o1;
            o0.x = acc[mi][ni][0] + bv.x; o0.y = acc[mi][ni][1] + bv.y;
            o1.x = acc[mi][ni][2] + bv.x; o1.y = acc[mi][ni][3] + bv.y;
            *(float2*)(C + (size_t)row0 * GN + col)       = o0;
            *(float2*)(C + (size_t)(row0 + 8) * GN + col) = o1;
        }
    }
}

// ---------------------------------------------------------------------------
// Banded attention v3: score phase as R6; V phase reads a STAGED smem V tile
// (reusing the Ks buffer after a sync) -> ~5.7x less L1tex traffic.
// ---------------------------------------------------------------------------
#define KSTR 68

__global__ __launch_bounds__(256) void attn_kernel(
    const float* __restrict__ q, const float* __restrict__ k,
    const float* __restrict__ v, const int* __restrict__ mask,
    float* __restrict__ out)
{
    constexpr int QT = 32;
    constexpr int KT = QT + 2 * PWH;  // 96
    __shared__ float Ks[KT * KSTR];   // K tile, later reused as V tile
    __shared__ float Qs[QT][PHD];
    __shared__ float Pr4[8][4][68];

    const int nqt = PS / QT;
    const int blk = blockIdx.x;
    const int qt = blk % nqt;
    const int h  = (blk / nqt) % PNH;
    const int b  = blk / (nqt * PNH);
    const int t0 = qt * QT;
    const int tid = threadIdx.x;
    const size_t base = ((size_t)b * PS) * PH + (size_t)h * PHD;

    for (int idx = tid; idx < KT * (PHD / 4); idx += 256) {
        int r  = idx >> 4;
        int c4 = (idx & 15) << 2;
        int jg = t0 - PWH + r;
        float4 kv = make_float4(0.f, 0.f, 0.f, 0.f);
        if (jg >= 0 && jg < PS)
            kv = *(const float4*)(k + base + (size_t)jg * PH + c4);
        *(float4*)(&Ks[r * KSTR + c4]) = kv;
    }
    for (int idx = tid; idx < QT * (PHD / 4); idx += 256) {
        int r  = idx >> 4;
        int c4 = (idx & 15) << 2;
        *(float4*)(&Qs[r][c4]) =
            *(const float4*)(q + base + (size_t)(t0 + r) * PH + c4);
    }
    __syncthreads();

    const int w = tid >> 5, l = tid & 31;
    const float inv_scale = 0.125f;

    #pragma unroll
    for (int qi = 0; qi < 4; qi++) {
        const int ql = 4 * w + qi;
        const int ig = t0 + ql;
        const int j0 = ig - PWH + l;
        const int j1 = j0 + 32;
        const int j2 = ig + PWH;
        const bool v0 = (j0 >= 0) && (j0 < PS) && (mask[b * PS + j0] != 0);
        const bool v1 = (j1 < PS) && (mask[b * PS + j1] != 0);
        const bool v2 = (j2 < PS) && (mask[b * PS + j2] != 0);

        const float4* K0 = (const float4*)(&Ks[(ql + l)      * KSTR]);
        const float4* K1 = (const float4*)(&Ks[(ql + l + 32) * KSTR]);
        const float4* K2 = (const float4*)(&Ks[(ql + 64)     * KSTR]);
        const float4* Qv = (const float4*)(&Qs[ql][0]);

        float s0 = 0.f, s1 = 0.f, s2 = 0.f;
        #pragma unroll
        for (int d4 = 0; d4 < PHD / 4; d4++) {
            float4 qv = Qv[d4];
            float4 a = K0[d4], c = K1[d4], e = K2[d4];
            s0 += qv.x * a.x + qv.y * a.y + qv.z * a.z + qv.w * a.w;
            s1 += qv.x * c.x + qv.y * c.y + qv.z * c.z + qv.w * c.w;
            s2 += qv.x * e.x + qv.y * e.y + qv.z * e.z + qv.w * e.w;
        }
        s0 = v0 ? s0 * inv_scale : -INFINITY;
        s1 = v1 ? s1 * inv_scale : -INFINITY;
        s2 = v2 ? s2 * inv_scale : -INFINITY;

        float m = fmaxf(fmaxf(s0, s1), s2);
        #pragma unroll
        for (int off = 16; off; off >>= 1)
            m = fmaxf(m, __shfl_xor_sync(0xffffffffu, m, off));

        const bool any = (m > -INFINITY);
        float e0 = (v0 && any) ? __expf(s0 - m) : 0.f;
        float e1 = (v1 && any) ? __expf(s1 - m) : 0.f;
        float e2 = (v2 && any) ? __expf(s2 - m) : 0.f;

        float ssum = e0 + e1;
        #pragma unroll
        for (int off = 16; off; off >>= 1)
            ssum += __shfl_xor_sync(0xffffffffu, ssum, off);
        ssum += e2;
        const float inv = any ? (1.0f / ssum) : 0.f;

        #pragma unroll
        for (int r = l; r < 68; r += 32) Pr4[w][qi][r] = 0.f;
        __syncwarp();
        Pr4[w][qi][qi + l]      = e0 * inv;
        Pr4[w][qi][qi + l + 32] = e1 * inv;
        if (l == 0) Pr4[w][qi][qi + 64] = e2 * inv;
        __syncwarp();
    }

    // ---- Stage V tile into the Ks buffer (scores are done with K) ----
    __syncthreads();
    for (int idx = tid; idx < KT * (PHD / 4); idx += 256) {
        int r  = idx >> 4;
        int c4 = (idx & 15) << 2;
        int jg = t0 - PWH + r;
        float4 vv = make_float4(0.f, 0.f, 0.f, 0.f);
        if (jg >= 0 && jg < PS)
            vv = *(const float4*)(v + base + (size_t)jg * PH + c4);
        *(float4*)(&Ks[r * KSTR + c4]) = vv;
    }
    __syncthreads();

    // ---- V pass from smem: warp's band = tile rows [4w, 4w+67] ----
    float2 a0 = make_float2(0.f, 0.f), a1 = a0, a2 = a0, a3 = a0;
    #pragma unroll 4
    for (int r = 0; r < 68; r++) {
        const float2 vv = *(const float2*)(&Ks[(4 * w + r) * KSTR + 2 * l]);
        const float p0 = Pr4[w][0][r];
        const float p1 = Pr4[w][1][r];
        const float p2 = Pr4[w][2][r];
        const float p3 = Pr4[w][3][r];
        a0.x += p0 * vv.x; a0.y += p0 * vv.y;
        a1.x += p1 * vv.x; a1.y += p1 * vv.y;
        a2.x += p2 * vv.x; a2.y += p2 * vv.y;
        a3.x += p3 * vv.x; a3.y += p3 * vv.y;
    }

    {
        const int ig0 = t0 + 4 * w;
        float* o = (float*)(out + base + (size_t)ig0 * PH + 2 * l);
        *(float2*)(o)          = a0;
        *(float2*)(o + PH)     = a1;
        *(float2*)(o + 2 * PH) = a2;
        *(float2*)(o + 3 * PH) = a3;
    }
}

// ---------------------------------------------------------------------------
extern "C" void kernel_launch(void* const* d_in, const int* in_sizes, int n_in,
                              void* d_out, int out_size)
{
    const float* x    = (const float*)d_in[0];
    const int*   mask = (const int*)  d_in[1];
    const float* Wq   = (const float*)d_in[2];
    const float* bq   = (const float*)d_in[3];
    const float* Wk   = (const float*)d_in[4];
    const float* bk   = (const float*)d_in[5];
    const float* Wv   = (const float*)d_in[6];
    const float* bv   = (const float*)d_in[7];
    const float* Wo   = (const float*)d_in[8];
    const float* bo   = (const float*)d_in[9];
    float* out = (float*)d_out;

    float *qp, *kp, *vp, *ap;
    cudaGetSymbolAddress((void**)&qp, g_q);
    cudaGetSymbolAddress((void**)&kp, g_k);
    cudaGetSymbolAddress((void**)&vp, g_v);
    cudaGetSymbolAddress((void**)&ap, g_a);

    // Fused Q/K/V projections: one launch, blockIdx.z selects operand set
    dim3 g3(GN / 128, PM / 128, 3);
    gemm_tf32_multi<<<g3, 256>>>(x, Wq, bq, qp, Wk, bk, kp, Wv, bv, vp);

    attn_kernel<<<PB * PNH * (PS / 32), 256>>>(qp, kp, vp, mask, ap);

    // O-projection: same kernel, single z-slice (all slots = same operands)
    dim3 g1(GN / 128, PM / 128, 1);
    gemm_tf32_multi<<<g1, 256>>>(ap, Wo, bo, out, Wo, bo, out, Wo, bo, out);
}

// round 11
// speedup vs baseline: 1.3614x; 1.3614x over previous
#include <cuda_runtime.h>
#include <cuda_bf16.h>
#include <math.h>
#include <stdint.h>

// Problem constants
#define PB   4
#define PS   2048
#define PH   1024      // hidden = NH*HD
#define PNH  16
#define PHD  64
#define PWH  32        // window half = WIN//2
#define PM   (PB*PS)   // 8192 GEMM rows

// Scratch (allocation-free): q, k, v, attn-out, each [B,S,NH*HD] fp32
#define SCR_ELEMS (PB*PS*PH)
__device__ float g_q[SCR_ELEMS];
__device__ float g_k[SCR_ELEMS];
__device__ float g_v[SCR_ELEMS];
__device__ float g_a[SCR_ELEMS];

// ---------------------------------------------------------------------------
// TF32 helpers
// ---------------------------------------------------------------------------
__device__ __forceinline__ float to_tf32(float x) {
    uint32_t u;
    asm("cvt.rna.tf32.f32 %0, %1;" : "=r"(u) : "f"(x));
    return __uint_as_float(u);
}

__device__ __forceinline__ void mma_tf32(float* c, const float* a, const float* b) {
    asm volatile(
        "mma.sync.aligned.m16n8k8.row.col.f32.tf32.tf32.f32 "
        "{%0,%1,%2,%3}, {%4,%5,%6,%7}, {%8,%9}, {%0,%1,%2,%3};"
        : "+f"(c[0]), "+f"(c[1]), "+f"(c[2]), "+f"(c[3])
        : "r"(__float_as_uint(a[0])), "r"(__float_as_uint(a[1])),
          "r"(__float_as_uint(a[2])), "r"(__float_as_uint(a[3])),
          "r"(__float_as_uint(b[0])), "r"(__float_as_uint(b[1])));
}

// ---------------------------------------------------------------------------
// GEMM v3 (TF32 mma.sync): C[M,1024] = A[M,1024] @ W[1024,1024] + bias
// 128x128 block, BK=32, 4 warps (2m x 2n), warp tile 64x64 -> fragment
// smem traffic per mma HALVED vs R6 (crossbar 768 vs 1024 cyc / CTA-tile).
// Strides SA=36 / SB=136: R6-proven conflict-free for both stores & frags.
// K-order identical to R6 -> bit-identical output.
// ---------------------------------------------------------------------------
#define GK 1024
#define GN 1024
#define SA 36
#define SB 136

__global__ __launch_bounds__(128) void gemm_tf32_kernel(
    const float* __restrict__ A, const float* __restrict__ W,
    const float* __restrict__ bias, float* __restrict__ C)
{
    __shared__ float As[128][SA];  // [m][k] 18432 B
    __shared__ float Bs[32][SB];   // [k][n] 17408 B  (35.8 KB total)

    const int tid = threadIdx.x;
    const int m0 = blockIdx.y * 128;
    const int n0 = blockIdx.x * 128;
    const int warp = tid >> 5;
    const int lane = tid & 31;
    const int g  = lane >> 2;   // 0..7
    const int tg = lane & 3;    // 0..3
    const int wm = (warp & 1) * 64;
    const int wn = (warp >> 1) * 64;

    float acc[4][8][4];
    #pragma unroll
    for (int mi = 0; mi < 4; mi++)
        #pragma unroll
        for (int ni = 0; ni < 8; ni++)
            #pragma unroll
            for (int r = 0; r < 4; r++) acc[mi][ni][r] = 0.f;

    const float* Ab = A + (size_t)m0 * GK;
    const float* Wb = W + n0;

    for (int k0 = 0; k0 < GK; k0 += 32) {
        // A tile: 128 x 32 = 1024 float4, 8 per thread; float4 STS (conflict-free)
        #pragma unroll
        for (int i = 0; i < 8; i++) {
            int idx = tid + i * 128;
            int r  = idx >> 3;
            int c4 = (idx & 7) << 2;
            float4 v = *(const float4*)(Ab + (size_t)r * GK + k0 + c4);
            v.x = to_tf32(v.x); v.y = to_tf32(v.y);
            v.z = to_tf32(v.z); v.w = to_tf32(v.w);
            *(float4*)(&As[r][c4]) = v;
        }
        // B tile: 32 x 128 = 1024 float4, 8 per thread
        #pragma unroll
        for (int i = 0; i < 8; i++) {
            int idx = tid + i * 128;
            int r  = idx >> 5;
            int c4 = (idx & 31) << 2;
            float4 v = *(const float4*)(Wb + (size_t)(k0 + r) * GN + c4);
            v.x = to_tf32(v.x); v.y = to_tf32(v.y);
            v.z = to_tf32(v.z); v.w = to_tf32(v.w);
            *(float4*)(&Bs[r][c4]) = v;
        }
        __syncthreads();

        #pragma unroll
        for (int ks = 0; ks < 4; ks++) {
            const int kb = ks * 8;
            float af[4][4], bf[8][2];
            #pragma unroll
            for (int mi = 0; mi < 4; mi++) {
                const int mr = wm + mi * 16 + g;
                af[mi][0] = As[mr    ][kb + tg];
                af[mi][1] = As[mr + 8][kb + tg];
                af[mi][2] = As[mr    ][kb + tg + 4];
                af[mi][3] = As[mr + 8][kb + tg + 4];
            }
            #pragma unroll
            for (int ni = 0; ni < 8; ni++) {
                const int nc = wn + ni * 8 + g;
                bf[ni][0] = Bs[kb + tg    ][nc];
                bf[ni][1] = Bs[kb + tg + 4][nc];
            }
            #pragma unroll
            for (int mi = 0; mi < 4; mi++)
                #pragma unroll
                for (int ni = 0; ni < 8; ni++)
                    mma_tf32(acc[mi][ni], af[mi], bf[ni]);
        }
        __syncthreads();
    }

    // Epilogue: bias + float2 stores
    #pragma unroll
    for (int mi = 0; mi < 4; mi++) {
        const int row0 = m0 + wm + mi * 16 + g;
        #pragma unroll
        for (int ni = 0; ni < 8; ni++) {
            const int col = n0 + wn + ni * 8 + tg * 2;
            const float2 bv = *(const float2*)(bias + col);
            float2 o0, o1;
            o0.x = acc[mi][ni][0] + bv.x; o0.y = acc[mi][ni][1] + bv.y;
            o1.x = acc[mi][ni][2] + bv.x; o1.y = acc[mi][ni][3] + bv.y;
            *(float2*)(C + (size_t)row0 * GN + col)       = o0;
            *(float2*)(C + (size_t)(row0 + 8) * GN + col) = o1;
        }
    }
}

// ---------------------------------------------------------------------------
// Banded attention: EXACT R6 v2 (measured 165.8us). Warp owns 4 consecutive
// queries; float4 score loads (stride 68); V-phase shares band rows across
// the warp's 4 queries with overlapped LDG.
// ---------------------------------------------------------------------------
#define KSTR 68

__global__ __launch_bounds__(256) void attn_kernel(
    const float* __restrict__ q, const float* __restrict__ k,
    const float* __restrict__ v, const int* __restrict__ mask,
    float* __restrict__ out)
{
    constexpr int QT = 32;
    constexpr int KT = QT + 2 * PWH;  // 96
    __shared__ float Ks[KT * KSTR];
    __shared__ float Qs[QT][PHD];
    __shared__ float Pr4[8][4][68];

    const int nqt = PS / QT;
    const int blk = blockIdx.x;
    const int qt = blk % nqt;
    const int h  = (blk / nqt) % PNH;
    const int b  = blk / (nqt * PNH);
    const int t0 = qt * QT;
    const int tid = threadIdx.x;
    const size_t base = ((size_t)b * PS) * PH + (size_t)h * PHD;

    for (int idx = tid; idx < KT * (PHD / 4); idx += 256) {
        int r  = idx >> 4;
        int c4 = (idx & 15) << 2;
        int jg = t0 - PWH + r;
        float4 kv = make_float4(0.f, 0.f, 0.f, 0.f);
        if (jg >= 0 && jg < PS)
            kv = *(const float4*)(k + base + (size_t)jg * PH + c4);
        *(float4*)(&Ks[r * KSTR + c4]) = kv;
    }
    for (int idx = tid; idx < QT * (PHD / 4); idx += 256) {
        int r  = idx >> 4;
        int c4 = (idx & 15) << 2;
        *(float4*)(&Qs[r][c4]) =
            *(const float4*)(q + base + (size_t)(t0 + r) * PH + c4);
    }
    __syncthreads();

    const int w = tid >> 5, l = tid & 31;
    const float inv_scale = 0.125f;

    #pragma unroll
    for (int qi = 0; qi < 4; qi++) {
        const int ql = 4 * w + qi;
        const int ig = t0 + ql;
        const int j0 = ig - PWH + l;
        const int j1 = j0 + 32;
        const int j2 = ig + PWH;
        const bool v0 = (j0 >= 0) && (j0 < PS) && (mask[b * PS + j0] != 0);
        const bool v1 = (j1 < PS) && (mask[b * PS + j1] != 0);
        const bool v2 = (j2 < PS) && (mask[b * PS + j2] != 0);

        const float4* K0 = (const float4*)(&Ks[(ql + l)      * KSTR]);
        const float4* K1 = (const float4*)(&Ks[(ql + l + 32) * KSTR]);
        const float4* K2 = (const float4*)(&Ks[(ql + 64)     * KSTR]);
        const float4* Qv = (const float4*)(&Qs[ql][0]);

        float s0 = 0.f, s1 = 0.f, s2 = 0.f;
        #pragma unroll
        for (int d4 = 0; d4 < PHD / 4; d4++) {
            float4 qv = Qv[d4];
            float4 a = K0[d4], c = K1[d4], e = K2[d4];
            s0 += qv.x * a.x + qv.y * a.y + qv.z * a.z + qv.w * a.w;
            s1 += qv.x * c.x + qv.y * c.y + qv.z * c.z + qv.w * c.w;
            s2 += qv.x * e.x + qv.y * e.y + qv.z * e.z + qv.w * e.w;
        }
        s0 = v0 ? s0 * inv_scale : -INFINITY;
        s1 = v1 ? s1 * inv_scale : -INFINITY;
        s2 = v2 ? s2 * inv_scale : -INFINITY;

        float m = fmaxf(fmaxf(s0, s1), s2);
        #pragma unroll
        for (int off = 16; off; off >>= 1)
            m = fmaxf(m, __shfl_xor_sync(0xffffffffu, m, off));

        const bool any = (m > -INFINITY);
        float e0 = (v0 && any) ? __expf(s0 - m) : 0.f;
        float e1 = (v1 && any) ? __expf(s1 - m) : 0.f;
        float e2 = (v2 && any) ? __expf(s2 - m) : 0.f;

        float ssum = e0 + e1;
        #pragma unroll
        for (int off = 16; off; off >>= 1)
            ssum += __shfl_xor_sync(0xffffffffu, ssum, off);
        ssum += e2;
        const float inv = any ? (1.0f / ssum) : 0.f;

        #pragma unroll
        for (int r = l; r < 68; r += 32) Pr4[w][qi][r] = 0.f;
        __syncwarp();
        Pr4[w][qi][qi + l]      = e0 * inv;
        Pr4[w][qi][qi + l + 32] = e1 * inv;
        if (l == 0) Pr4[w][qi][qi + 64] = e2 * inv;
        __syncwarp();
    }

    const int r0g = t0 + 4 * w - PWH;
    float2 a0 = make_float2(0.f, 0.f), a1 = a0, a2 = a0, a3 = a0;

    #pragma unroll 4
    for (int r = 0; r < 68; r++) {
        int jg = r0g + r;
        jg = min(max(jg, 0), PS - 1);
        const float2 vv = *(const float2*)(v + base + (size_t)jg * PH + 2 * l);
        const float p0 = Pr4[w][0][r];
        const float p1 = Pr4[w][1][r];
        const float p2 = Pr4[w][2][r];
        const float p3 = Pr4[w][3][r];
        a0.x += p0 * vv.x; a0.y += p0 * vv.y;
        a1.x += p1 * vv.x; a1.y += p1 * vv.y;
        a2.x += p2 * vv.x; a2.y += p2 * vv.y;
        a3.x += p3 * vv.x; a3.y += p3 * vv.y;
    }

    {
        const int ig0 = t0 + 4 * w;
        float* o = (float*)(out + base + (size_t)ig0 * PH + 2 * l);
        *(float2*)(o)          = a0;
        *(float2*)(o + PH)     = a1;
        *(float2*)(o + 2 * PH) = a2;
        *(float2*)(o + 3 * PH) = a3;
    }
}

// ---------------------------------------------------------------------------
extern "C" void kernel_launch(void* const* d_in, const int* in_sizes, int n_in,
                              void* d_out, int out_size)
{
    const float* x    = (const float*)d_in[0];
    const int*   mask = (const int*)  d_in[1];
    const float* Wq   = (const float*)d_in[2];
    const float* bq   = (const float*)d_in[3];
    const float* Wk   = (const float*)d_in[4];
    const float* bk   = (const float*)d_in[5];
    const float* Wv   = (const float*)d_in[6];
    const float* bv   = (const float*)d_in[7];
    const float* Wo   = (const float*)d_in[8];
    const float* bo   = (const float*)d_in[9];
    float* out = (float*)d_out;

    float *qp, *kp, *vp, *ap;
    cudaGetSymbolAddress((void**)&qp, g_q);
    cudaGetSymbolAddress((void**)&kp, g_k);
    cudaGetSymbolAddress((void**)&vp, g_v);
    cudaGetSymbolAddress((void**)&ap, g_a);

    dim3 ggrid(GN / 128, PM / 128);  // (8, 64)
    gemm_tf32_kernel<<<ggrid, 128>>>(x, Wq, bq, qp);
    gemm_tf32_kernel<<<ggrid, 128>>>(x, Wk, bk, kp);
    gemm_tf32_kernel<<<ggrid, 128>>>(x, Wv, bv, vp);

    attn_kernel<<<PB * PNH * (PS / 32), 256>>>(qp, kp, vp, mask, ap);

    gemm_tf32_kernel<<<ggrid, 128>>>(ap, Wo, bo, out);
}

// round 13
// speedup vs baseline: 2.5038x; 1.8391x over previous
#include <cuda_runtime.h>
#include <cuda_fp16.h>
#include <math.h>
#include <stdint.h>

// Problem constants
#define PB   4
#define PS   2048
#define PH   1024      // hidden = NH*HD
#define PNH  16
#define PHD  64
#define PWH  32        // window half = WIN//2
#define PM   (PB*PS)   // 8192 GEMM rows

// Scratch (allocation-free): q, k, v, attn-out, each [B,S,NH*HD] fp32
#define SCR_ELEMS (PB*PS*PH)
__device__ float g_q[SCR_ELEMS];
__device__ float g_k[SCR_ELEMS];
__device__ float g_v[SCR_ELEMS];
__device__ float g_a[SCR_ELEMS];

// ---------------------------------------------------------------------------
// fp16 mma helper (m16n8k16, fp32 accumulate)
// ---------------------------------------------------------------------------
__device__ __forceinline__ void mma_f16(float* c, const uint32_t* a,
                                        const uint32_t* b) {
    asm volatile(
        "mma.sync.aligned.m16n8k16.row.col.f32.f16.f16.f32 "
        "{%0,%1,%2,%3}, {%4,%5,%6,%7}, {%8,%9}, {%0,%1,%2,%3};"
        : "+f"(c[0]), "+f"(c[1]), "+f"(c[2]), "+f"(c[3])
        : "r"(a[0]), "r"(a[1]), "r"(a[2]), "r"(a[3]),
          "r"(b[0]), "r"(b[1]));
}

__device__ __forceinline__ uint32_t pack_h2(float lo, float hi) {
    __half2 h = __floats2half2_rn(lo, hi);
    return *(uint32_t*)&h;
}

// ---------------------------------------------------------------------------
// GEMM v4 (fp16 mma m16n8k16): C[M,1024] = A @ W + bias.
// R6 shape: 128x128 CTA tile, BK=32, 8 warps (2m x 4n), warp tile 64x32.
// Half the mma.sync count of the tf32 version at the same issue rate.
// As2: [m][k-pair] stride 20 half2  -> frag banks (20g+tg)%32 bijective.
// Bs2: [k-pair][n] stride 136 half2 -> frag banks (8tg+g)%32 bijective.
// ---------------------------------------------------------------------------
#define GK 1024
#define GN 1024
#define SAH2 20
#define SBH2 136

__global__ __launch_bounds__(256) void gemm_f16_kernel(
    const float* __restrict__ A, const float* __restrict__ W,
    const float* __restrict__ bias, float* __restrict__ C)
{
    __shared__ uint32_t As2[128 * SAH2];  // 10240 B (half2 elements)
    __shared__ uint32_t Bs2[16 * SBH2];   //  8704 B

    const int tid = threadIdx.x;
    const int m0 = blockIdx.y * 128;
    const int n0 = blockIdx.x * 128;
    const int warp = tid >> 5;
    const int lane = tid & 31;
    const int g  = lane >> 2;   // 0..7
    const int tg = lane & 3;    // 0..3
    const int wm = (warp & 1) * 64;
    const int wn = (warp >> 1) * 32;

    float acc[4][4][4];
    #pragma unroll
    for (int mi = 0; mi < 4; mi++)
        #pragma unroll
        for (int ni = 0; ni < 4; ni++)
            #pragma unroll
            for (int r = 0; r < 4; r++) acc[mi][ni][r] = 0.f;

    const float* Ab = A + (size_t)m0 * GK;
    const float* Wb = W + n0;

    for (int k0 = 0; k0 < GK; k0 += 32) {
        // A tile: 128 rows x 32 k = 1024 float4 units, 4/thread.
        // Pack (k,k+1) pairs into half2; 8B store per unit.
        #pragma unroll
        for (int i = 0; i < 4; i++) {
            int idx = tid + (i << 8);
            int r  = idx >> 3;
            int c4 = (idx & 7) << 2;             // k offset (floats)
            float4 v = *(const float4*)(Ab + (size_t)r * GK + k0 + c4);
            uint2 u;
            u.x = pack_h2(v.x, v.y);
            u.y = pack_h2(v.z, v.w);
            *(uint2*)(&As2[r * SAH2 + (c4 >> 1)]) = u;
        }
        // B tile: 32 k rows x 128 n; pack k-pairs (2kk, 2kk+1) along n.
        // 512 units (16 kk x 32 col-groups), 2/thread; 16B store per unit.
        #pragma unroll
        for (int i = 0; i < 2; i++) {
            int idx = tid + (i << 8);
            int kk = idx >> 5;                   // 0..15
            int c4 = (idx & 31) << 2;            // 0..124
            const float* r0p = Wb + (size_t)(k0 + 2 * kk) * GN + c4;
            const float* r1p = r0p + GN;
            float4 v0 = *(const float4*)r0p;
            float4 v1 = *(const float4*)r1p;
            uint4 u;
            u.x = pack_h2(v0.x, v1.x);
            u.y = pack_h2(v0.y, v1.y);
            u.z = pack_h2(v0.z, v1.z);
            u.w = pack_h2(v0.w, v1.w);
            *(uint4*)(&Bs2[kk * SBH2 + c4]) = u;
        }
        __syncthreads();

        #pragma unroll
        for (int ks = 0; ks < 2; ks++) {
            const int kb = ks * 8;               // half2 offset of this 16-k
            uint32_t af[4][4], bf[4][2];
            #pragma unroll
            for (int mi = 0; mi < 4; mi++) {
                const int mr = wm + mi * 16 + g;
                af[mi][0] = As2[mr * SAH2       + kb + tg];
                af[mi][1] = As2[(mr + 8) * SAH2 + kb + tg];
                af[mi][2] = As2[mr * SAH2       + kb + tg + 4];
                af[mi][3] = As2[(mr + 8) * SAH2 + kb + tg + 4];
            }
            #pragma unroll
            for (int ni = 0; ni < 4; ni++) {
                const int nc = wn + ni * 8 + g;
                bf[ni][0] = Bs2[(kb + tg) * SBH2     + nc];
                bf[ni][1] = Bs2[(kb + tg + 4) * SBH2 + nc];
            }
            #pragma unroll
            for (int mi = 0; mi < 4; mi++)
                #pragma unroll
                for (int ni = 0; ni < 4; ni++)
                    mma_f16(acc[mi][ni], af[mi], bf[ni]);
        }
        __syncthreads();
    }

    // Epilogue: bias + float2 stores (fp32 accumulators)
    #pragma unroll
    for (int mi = 0; mi < 4; mi++) {
        const int row0 = m0 + wm + mi * 16 + g;
        #pragma unroll
        for (int ni = 0; ni < 4; ni++) {
            const int col = n0 + wn + ni * 8 + tg * 2;
            const float2 bv = *(const float2*)(bias + col);
            float2 o0, o1;
            o0.x = acc[mi][ni][0] + bv.x; o0.y = acc[mi][ni][1] + bv.y;
            o1.x = acc[mi][ni][2] + bv.x; o1.y = acc[mi][ni][3] + bv.y;
            *(float2*)(C + (size_t)row0 * GN + col)       = o0;
            *(float2*)(C + (size_t)(row0 + 8) * GN + col) = o1;
        }
    }
}

// ---------------------------------------------------------------------------
// Banded attention: EXACT R6 v2 (measured 165.8-166.8us across 3 runs).
// ---------------------------------------------------------------------------
#define KSTR 68

__global__ __launch_bounds__(256) void attn_kernel(
    const float* __restrict__ q, const float* __restrict__ k,
    const float* __restrict__ v, const int* __restrict__ mask,
    float* __restrict__ out)
{
    constexpr int QT = 32;
    constexpr int KT = QT + 2 * PWH;  // 96
    __shared__ float Ks[KT * KSTR];
    __shared__ float Qs[QT][PHD];
    __shared__ float Pr4[8][4][68];

    const int nqt = PS / QT;
    const int blk = blockIdx.x;
    const int qt = blk % nqt;
    const int h  = (blk / nqt) % PNH;
    const int b  = blk / (nqt * PNH);
    const int t0 = qt * QT;
    const int tid = threadIdx.x;
    const size_t base = ((size_t)b * PS) * PH + (size_t)h * PHD;

    for (int idx = tid; idx < KT * (PHD / 4); idx += 256) {
        int r  = idx >> 4;
        int c4 = (idx & 15) << 2;
        int jg = t0 - PWH + r;
        float4 kv = make_float4(0.f, 0.f, 0.f, 0.f);
        if (jg >= 0 && jg < PS)
            kv = *(const float4*)(k + base + (size_t)jg * PH + c4);
        *(float4*)(&Ks[r * KSTR + c4]) = kv;
    }
    for (int idx = tid; idx < QT * (PHD / 4); idx += 256) {
        int r  = idx >> 4;
        int c4 = (idx & 15) << 2;
        *(float4*)(&Qs[r][c4]) =
            *(const float4*)(q + base + (size_t)(t0 + r) * PH + c4);
    }
    __syncthreads();

    const int w = tid >> 5, l = tid & 31;
    const float inv_scale = 0.125f;

    #pragma unroll
    for (int qi = 0; qi < 4; qi++) {
        const int ql = 4 * w + qi;
        const int ig = t0 + ql;
        const int j0 = ig - PWH + l;
        const int j1 = j0 + 32;
        const int j2 = ig + PWH;
        const bool v0 = (j0 >= 0) && (j0 < PS) && (mask[b * PS + j0] != 0);
        const bool v1 = (j1 < PS) && (mask[b * PS + j1] != 0);
        const bool v2 = (j2 < PS) && (mask[b * PS + j2] != 0);

        const float4* K0 = (const float4*)(&Ks[(ql + l)      * KSTR]);
        const float4* K1 = (const float4*)(&Ks[(ql + l + 32) * KSTR]);
        const float4* K2 = (const float4*)(&Ks[(ql + 64)     * KSTR]);
        const float4* Qv = (const float4*)(&Qs[ql][0]);

        float s0 = 0.f, s1 = 0.f, s2 = 0.f;
        #pragma unroll
        for (int d4 = 0; d4 < PHD / 4; d4++) {
            float4 qv = Qv[d4];
            float4 a = K0[d4], c = K1[d4], e = K2[d4];
            s0 += qv.x * a.x + qv.y * a.y + qv.z * a.z + qv.w * a.w;
            s1 += qv.x * c.x + qv.y * c.y + qv.z * c.z + qv.w * c.w;
            s2 += qv.x * e.x + qv.y * e.y + qv.z * e.z + qv.w * e.w;
        }
        s0 = v0 ? s0 * inv_scale : -INFINITY;
        s1 = v1 ? s1 * inv_scale : -INFINITY;
        s2 = v2 ? s2 * inv_scale : -INFINITY;

        float m = fmaxf(fmaxf(s0, s1), s2);
        #pragma unroll
        for (int off = 16; off; off >>= 1)
            m = fmaxf(m, __shfl_xor_sync(0xffffffffu, m, off));

        const bool any = (m > -INFINITY);
        float e0 = (v0 && any) ? __expf(s0 - m) : 0.f;
        float e1 = (v1 && any) ? __expf(s1 - m) : 0.f;
        float e2 = (v2 && any) ? __expf(s2 - m) : 0.f;

        float ssum = e0 + e1;
        #pragma unroll
        for (int off = 16; off; off >>= 1)
            ssum += __shfl_xor_sync(0xffffffffu, ssum, off);
        ssum += e2;
        const float inv = any ? (1.0f / ssum) : 0.f;

        #pragma unroll
        for (int r = l; r < 68; r += 32) Pr4[w][qi][r] = 0.f;
        __syncwarp();
        Pr4[w][qi][qi + l]      = e0 * inv;
        Pr4[w][qi][qi + l + 32] = e1 * inv;
        if (l == 0) Pr4[w][qi][qi + 64] = e2 * inv;
        __syncwarp();
    }

    const int r0g = t0 + 4 * w - PWH;
    float2 a0 = make_float2(0.f, 0.f), a1 = a0, a2 = a0, a3 = a0;

    #pragma unroll 4
    for (int r = 0; r < 68; r++) {
        int jg = r0g + r;
        jg = min(max(jg, 0), PS - 1);
        const float2 vv = *(const float2*)(v + base + (size_t)jg * PH + 2 * l);
        const float p0 = Pr4[w][0][r];
        const float p1 = Pr4[w][1][r];
        const float p2 = Pr4[w][2][r];
        const float p3 = Pr4[w][3][r];
        a0.x += p0 * vv.x; a0.y += p0 * vv.y;
        a1.x += p1 * vv.x; a1.y += p1 * vv.y;
        a2.x += p2 * vv.x; a2.y += p2 * vv.y;
        a3.x += p3 * vv.x; a3.y += p3 * vv.y;
    }

    {
        const int ig0 = t0 + 4 * w;
        float* o = (float*)(out + base + (size_t)ig0 * PH + 2 * l);
        *(float2*)(o)          = a0;
        *(float2*)(o + PH)     = a1;
        *(float2*)(o + 2 * PH) = a2;
        *(float2*)(o + 3 * PH) = a3;
    }
}

// ---------------------------------------------------------------------------
extern "C" void kernel_launch(void* const* d_in, const int* in_sizes, int n_in,
                              void* d_out, int out_size)
{
    const float* x    = (const float*)d_in[0];
    const int*   mask = (const int*)  d_in[1];
    const float* Wq   = (const float*)d_in[2];
    const float* bq   = (const float*)d_in[3];
    const float* Wk   = (const float*)d_in[4];
    const float* bk   = (const float*)d_in[5];
    const float* Wv   = (const float*)d_in[6];
    const float* bv   = (const float*)d_in[7];
    const float* Wo   = (const float*)d_in[8];
    const float* bo   = (const float*)d_in[9];
    float* out = (float*)d_out;

    float *qp, *kp, *vp, *ap;
    cudaGetSymbolAddress((void**)&qp, g_q);
    cudaGetSymbolAddress((void**)&kp, g_k);
    cudaGetSymbolAddress((void**)&vp, g_v);
    cudaGetSymbolAddress((void**)&ap, g_a);

    dim3 ggrid(GN / 128, PM / 128);  // (8, 64)
    gemm_f16_kernel<<<ggrid, 256>>>(x, Wq, bq, qp);
    gemm_f16_kernel<<<ggrid, 256>>>(x, Wk, bk, kp);
    gemm_f16_kernel<<<ggrid, 256>>>(x, Wv, bv, vp);

    attn_kernel<<<PB * PNH * (PS / 32), 256>>>(qp, kp, vp, mask, ap);

    gemm_f16_kernel<<<ggrid, 256>>>(ap, Wo, bo, out);
}

// round 15
// speedup vs baseline: 2.7439x; 1.0959x over previous
#include <cuda_runtime.h>
#include <cuda_fp16.h>
#include <math.h>
#include <stdint.h>

// Problem constants
#define PB   4
#define PS   2048
#define PH   1024      // hidden = NH*HD
#define PNH  16
#define PHD  64
#define PWH  32        // window half = WIN//2
#define PM   (PB*PS)   // 8192 GEMM rows

// Scratch (allocation-free)
#define SCR_ELEMS (PB*PS*PH)
__device__ float   g_q[SCR_ELEMS];
__device__ float   g_k[SCR_ELEMS];
__device__ float   g_v[SCR_ELEMS];
__device__ __half  g_xh[SCR_ELEMS];      // x as fp16 rows (GEMM A-side)
__device__ __half  g_ah[SCR_ELEMS];      // attn out as fp16 rows (A-side of O-proj)
__device__ uint32_t g_wqp[PH*PH/2];      // W packed [k-pair][n] half2 (B-side)
__device__ uint32_t g_wkp[PH*PH/2];
__device__ uint32_t g_wvp[PH*PH/2];
__device__ uint32_t g_wop[PH*PH/2];

// ---------------------------------------------------------------------------
// Helpers
// ---------------------------------------------------------------------------
__device__ __forceinline__ void mma_f16(float* c, const uint32_t* a,
                                        const uint32_t* b) {
    asm volatile(
        "mma.sync.aligned.m16n8k16.row.col.f32.f16.f16.f32 "
        "{%0,%1,%2,%3}, {%4,%5,%6,%7}, {%8,%9}, {%0,%1,%2,%3};"
        : "+f"(c[0]), "+f"(c[1]), "+f"(c[2]), "+f"(c[3])
        : "r"(a[0]), "r"(a[1]), "r"(a[2]), "r"(a[3]),
          "r"(b[0]), "r"(b[1]));
}

__device__ __forceinline__ uint32_t pack_h2(float lo, float hi) {
    __half2 h = __floats2half2_rn(lo, hi);
    return *(uint32_t*)&h;
}

__device__ __forceinline__ void cp16(void* smem_dst, const void* gmem_src) {
    uint32_t d = (uint32_t)__cvta_generic_to_shared(smem_dst);
    asm volatile("cp.async.ca.shared.global [%0], [%1], 16;\n"
                 :: "r"(d), "l"(gmem_src));
}

// ---------------------------------------------------------------------------
// Pre-passes (RN conversions identical to the previous in-GEMM path)
// ---------------------------------------------------------------------------
__global__ __launch_bounds__(256) void f32_to_f16_kernel(
    const float* __restrict__ in, __half* __restrict__ out, int n4)
{
    int i = blockIdx.x * 256 + threadIdx.x;
    if (i < n4) {
        float4 v = ((const float4*)in)[i];
        uint2 u;
        u.x = pack_h2(v.x, v.y);
        u.y = pack_h2(v.z, v.w);
        ((uint2*)out)[i] = u;
    }
}

// Wp[kk*1024 + n] = half2(W[2kk][n], W[2kk+1][n])
__global__ __launch_bounds__(256) void pack_w_kernel(
    const float* __restrict__ W, uint32_t* __restrict__ Wp)
{
    int idx = blockIdx.x * 256 + threadIdx.x;   // 512*1024 total
    int kk = idx >> 10, n = idx & 1023;
    float a = W[(size_t)(2 * kk) * PH + n];
    float b = W[(size_t)(2 * kk + 1) * PH + n];
    Wp[(size_t)kk * PH + n] = pack_h2(a, b);
}

// ---------------------------------------------------------------------------
// GEMM v5 (fp16 mma m16n8k16, cp.async 2-stage): C[M,1024] = A @ W + bias.
// A = fp16 rows, Wp = packed [kpair][n] half2. 128x128 CTA, BK=32, 8 warps.
// Fragment/mma code identical to R13; only staging changed.
// ---------------------------------------------------------------------------
#define GK 1024
#define GN 1024
#define SAH2 20
#define SBH2 136
#define NIT 32

__global__ __launch_bounds__(256) void gemm_f16_db(
    const __half* __restrict__ A, const uint32_t* __restrict__ Wp,
    const float* __restrict__ bias, float* __restrict__ C)
{
    __shared__ uint32_t As2[2][128 * SAH2];  // 2 x 10240 B
    __shared__ uint32_t Bs2[2][16 * SBH2];   // 2 x  8704 B

    const int tid = threadIdx.x;
    const int m0 = blockIdx.y * 128;
    const int n0 = blockIdx.x * 128;
    const int warp = tid >> 5;
    const int lane = tid & 31;
    const int g  = lane >> 2;
    const int tg = lane & 3;
    const int wm = (warp & 1) * 64;
    const int wn = (warp >> 1) * 32;

    float acc[4][4][4];
    #pragma unroll
    for (int mi = 0; mi < 4; mi++)
        #pragma unroll
        for (int ni = 0; ni < 4; ni++)
            #pragma unroll
            for (int r = 0; r < 4; r++) acc[mi][ni][r] = 0.f;

    const __half* Ab = A + (size_t)m0 * GK;

    auto load_stage = [&](int s, int k0) {
        // A: 512 chunks of 16B (8 halves). r = row, c = 16B chunk in row.
        #pragma unroll
        for (int i = 0; i < 2; i++) {
            int id = tid + (i << 8);
            int r = id >> 2, c = id & 3;
            cp16(&As2[s][r * SAH2 + c * 4],
                 Ab + (size_t)r * GK + k0 + c * 8);
        }
        // B: 512 chunks of 16B (4 half2 cols). kk = local k-pair row.
        #pragma unroll
        for (int i = 0; i < 2; i++) {
            int id = tid + (i << 8);
            int kk = id >> 5, c = id & 31;
            cp16(&Bs2[s][kk * SBH2 + c * 4],
                 Wp + (size_t)((k0 >> 1) + kk) * GN + n0 + c * 4);
        }
        asm volatile("cp.async.commit_group;\n" ::: "memory");
    };

    load_stage(0, 0);

    for (int it = 0; it < NIT; it++) {
        if (it + 1 < NIT) {
            load_stage((it + 1) & 1, (it + 1) * 32);
            asm volatile("cp.async.wait_group 1;\n" ::: "memory");
        } else {
            asm volatile("cp.async.wait_group 0;\n" ::: "memory");
        }
        __syncthreads();

        const int s = it & 1;
        #pragma unroll
        for (int ks = 0; ks < 2; ks++) {
            const int kb = ks * 8;
            uint32_t af[4][4], bf[4][2];
            #pragma unroll
            for (int mi = 0; mi < 4; mi++) {
                const int mr = wm + mi * 16 + g;
                af[mi][0] = As2[s][mr * SAH2       + kb + tg];
                af[mi][1] = As2[s][(mr + 8) * SAH2 + kb + tg];
                af[mi][2] = As2[s][mr * SAH2       + kb + tg + 4];
                af[mi][3] = As2[s][(mr + 8) * SAH2 + kb + tg + 4];
            }
            #pragma unroll
            for (int ni = 0; ni < 4; ni++) {
                const int nc = wn + ni * 8 + g;
                bf[ni][0] = Bs2[s][(kb + tg) * SBH2     + nc];
                bf[ni][1] = Bs2[s][(kb + tg + 4) * SBH2 + nc];
            }
            #pragma unroll
            for (int mi = 0; mi < 4; mi++)
                #pragma unroll
                for (int ni = 0; ni < 4; ni++)
                    mma_f16(acc[mi][ni], af[mi], bf[ni]);
        }
        __syncthreads();
    }

    // Epilogue: bias + float2 stores (fp32 accumulators)
    #pragma unroll
    for (int mi = 0; mi < 4; mi++) {
        const int row0 = m0 + wm + mi * 16 + g;
        #pragma unroll
        for (int ni = 0; ni < 4; ni++) {
            const int col = n0 + wn + ni * 8 + tg * 2;
            const float2 bv = *(const float2*)(bias + col);
            float2 o0, o1;
            o0.x = acc[mi][ni][0] + bv.x; o0.y = acc[mi][ni][1] + bv.y;
            o1.x = acc[mi][ni][2] + bv.x; o1.y = acc[mi][ni][3] + bv.y;
            *(float2*)(C + (size_t)row0 * GN + col)       = o0;
            *(float2*)(C + (size_t)(row0 + 8) * GN + col) = o1;
        }
    }
}

// ---------------------------------------------------------------------------
// Banded attention (R6 core, measured 166us): unchanged except the epilogue
// stores packed fp16 (same RN conversion the O-proj GEMM applied before).
// ---------------------------------------------------------------------------
#define KSTR 68

__global__ __launch_bounds__(256) void attn_kernel(
    const float* __restrict__ q, const float* __restrict__ k,
    const float* __restrict__ v, const int* __restrict__ mask,
    __half* __restrict__ out)
{
    constexpr int QT = 32;
    constexpr int KT = QT + 2 * PWH;  // 96
    __shared__ float Ks[KT * KSTR];
    __shared__ float Qs[QT][PHD];
    __shared__ float Pr4[8][4][68];

    const int nqt = PS / QT;
    const int blk = blockIdx.x;
    const int qt = blk % nqt;
    const int h  = (blk / nqt) % PNH;
    const int b  = blk / (nqt * PNH);
    const int t0 = qt * QT;
    const int tid = threadIdx.x;
    const size_t base = ((size_t)b * PS) * PH + (size_t)h * PHD;

    for (int idx = tid; idx < KT * (PHD / 4); idx += 256) {
        int r  = idx >> 4;
        int c4 = (idx & 15) << 2;
        int jg = t0 - PWH + r;
        float4 kv = make_float4(0.f, 0.f, 0.f, 0.f);
        if (jg >= 0 && jg < PS)
            kv = *(const float4*)(k + base + (size_t)jg * PH + c4);
        *(float4*)(&Ks[r * KSTR + c4]) = kv;
    }
    for (int idx = tid; idx < QT * (PHD / 4); idx += 256) {
        int r  = idx >> 4;
        int c4 = (idx & 15) << 2;
        *(float4*)(&Qs[r][c4]) =
            *(const float4*)(q + base + (size_t)(t0 + r) * PH + c4);
    }
    __syncthreads();

    const int w = tid >> 5, l = tid & 31;
    const float inv_scale = 0.125f;

    #pragma unroll
    for (int qi = 0; qi < 4; qi++) {
        const int ql = 4 * w + qi;
        const int ig = t0 + ql;
        const int j0 = ig - PWH + l;
        const int j1 = j0 + 32;
        const int j2 = ig + PWH;
        const bool v0 = (j0 >= 0) && (j0 < PS) && (mask[b * PS + j0] != 0);
        const bool v1 = (j1 < PS) && (mask[b * PS + j1] != 0);
        const bool v2 = (j2 < PS) && (mask[b * PS + j2] != 0);

        const float4* K0 = (const float4*)(&Ks[(ql + l)      * KSTR]);
        const float4* K1 = (const float4*)(&Ks[(ql + l + 32) * KSTR]);
        const float4* K2 = (const float4*)(&Ks[(ql + 64)     * KSTR]);
        const float4* Qv = (const float4*)(&Qs[ql][0]);

        float s0 = 0.f, s1 = 0.f, s2 = 0.f;
        #pragma unroll
        for (int d4 = 0; d4 < PHD / 4; d4++) {
            float4 qv = Qv[d4];
            float4 a = K0[d4], c = K1[d4], e = K2[d4];
            s0 += qv.x * a.x + qv.y * a.y + qv.z * a.z + qv.w * a.w;
            s1 += qv.x * c.x + qv.y * c.y + qv.z * c.z + qv.w * c.w;
            s2 += qv.x * e.x + qv.y * e.y + qv.z * e.z + qv.w * e.w;
        }
        s0 = v0 ? s0 * inv_scale : -INFINITY;
        s1 = v1 ? s1 * inv_scale : -INFINITY;
        s2 = v2 ? s2 * inv_scale : -INFINITY;

        float m = fmaxf(fmaxf(s0, s1), s2);
        #pragma unroll
        for (int off = 16; off; off >>= 1)
            m = fmaxf(m, __shfl_xor_sync(0xffffffffu, m, off));

        const bool any = (m > -INFINITY);
        float e0 = (v0 && any) ? __expf(s0 - m) : 0.f;
        float e1 = (v1 && any) ? __expf(s1 - m) : 0.f;
        float e2 = (v2 && any) ? __expf(s2 - m) : 0.f;

        float ssum = e0 + e1;
        #pragma unroll
        for (int off = 16; off; off >>= 1)
            ssum += __shfl_xor_sync(0xffffffffu, ssum, off);
        ssum += e2;
        const float inv = any ? (1.0f / ssum) : 0.f;

        #pragma unroll
        for (int r = l; r < 68; r += 32) Pr4[w][qi][r] = 0.f;
        __syncwarp();
        Pr4[w][qi][qi + l]      = e0 * inv;
        Pr4[w][qi][qi + l + 32] = e1 * inv;
        if (l == 0) Pr4[w][qi][qi + 64] = e2 * inv;
        __syncwarp();
    }

    const int r0g = t0 + 4 * w - PWH;
    float2 a0 = make_float2(0.f, 0.f), a1 = a0, a2 = a0, a3 = a0;

    #pragma unroll 4
    for (int r = 0; r < 68; r++) {
        int jg = r0g + r;
        jg = min(max(jg, 0), PS - 1);
        const float2 vv = *(const float2*)(v + base + (size_t)jg * PH + 2 * l);
        const float p0 = Pr4[w][0][r];
        const float p1 = Pr4[w][1][r];
        const float p2 = Pr4[w][2][r];
        const float p3 = Pr4[w][3][r];
        a0.x += p0 * vv.x; a0.y += p0 * vv.y;
        a1.x += p1 * vv.x; a1.y += p1 * vv.y;
        a2.x += p2 * vv.x; a2.y += p2 * vv.y;
        a3.x += p3 * vv.x; a3.y += p3 * vv.y;
    }

    {
        const int ig0 = t0 + 4 * w;
        uint32_t* o = (uint32_t*)(out + base + (size_t)ig0 * PH + 2 * l);
        o[0]                 = pack_h2(a0.x, a0.y);
        o[PH / 2]            = pack_h2(a1.x, a1.y);
        o[PH]                = pack_h2(a2.x, a2.y);
        o[3 * PH / 2]        = pack_h2(a3.x, a3.y);
    }
}

// ---------------------------------------------------------------------------
extern "C" void kernel_launch(void* const* d_in, const int* in_sizes, int n_in,
                              void* d_out, int out_size)
{
    const float* x    = (const float*)d_in[0];
    const int*   mask = (const int*)  d_in[1];
    const float* Wq   = (const float*)d_in[2];
    const float* bq   = (const float*)d_in[3];
    const float* Wk   = (const float*)d_in[4];
    const float* bk   = (const float*)d_in[5];
    const float* Wv   = (const float*)d_in[6];
    const float* bv   = (const float*)d_in[7];
    const float* Wo   = (const float*)d_in[8];
    const float* bo   = (const float*)d_in[9];
    float* out = (float*)d_out;

    float *qp, *kp, *vp;
    __half *xh, *ah;
    uint32_t *wqp, *wkp, *wvp, *wop;
    cudaGetSymbolAddress((void**)&qp,  g_q);
    cudaGetSymbolAddress((void**)&kp,  g_k);
    cudaGetSymbolAddress((void**)&vp,  g_v);
    cudaGetSymbolAddress((void**)&xh,  g_xh);
    cudaGetSymbolAddress((void**)&ah,  g_ah);
    cudaGetSymbolAddress((void**)&wqp, g_wqp);
    cudaGetSymbolAddress((void**)&wkp, g_wkp);
    cudaGetSymbolAddress((void**)&wvp, g_wvp);
    cudaGetSymbolAddress((void**)&wop, g_wop);

    // Pre-passes
    const int nx4 = SCR_ELEMS / 4;
    f32_to_f16_kernel<<<(nx4 + 255) / 256, 256>>>(x, xh, nx4);
    const int nw = PH * PH / 2;
    pack_w_kernel<<<nw / 256, 256>>>(Wq, wqp);
    pack_w_kernel<<<nw / 256, 256>>>(Wk, wkp);
    pack_w_kernel<<<nw / 256, 256>>>(Wv, wvp);
    pack_w_kernel<<<nw / 256, 256>>>(Wo, wop);

    dim3 ggrid(GN / 128, PM / 128);  // (8, 64)
    gemm_f16_db<<<ggrid, 256>>>(xh, wqp, bq, qp);
    gemm_f16_db<<<ggrid, 256>>>(xh, wkp, bk, kp);
    gemm_f16_db<<<ggrid, 256>>>(xh, wvp, bv, vp);

    attn_kernel<<<PB * PNH * (PS / 32), 256>>>(qp, kp, vp, mask, ah);

    gemm_f16_db<<<ggrid, 256>>>(ah, wop, bo, out);
}